// round 12
// baseline (speedup 1.0000x reference)
#include <cuda_runtime.h>
#include <cuda_fp16.h>

// Deform_Conv_V1: fused offset-conv + deformable conv + ReLU.
// B=8, Cin=32, H=W=160, Cout=32, K=3, PAD=1.
// Inputs: x (8,32,160,160), w_off (18,32,3,3), b_off (18,), w_dcn (32,32,3,3)
// Output: (8,32,160,160) fp32.
//
// R12: 4 pixels/thread (px = base+tid+128p) halves per-pixel constant-port
//      LDC vs R7. All weights in __constant__ (R5/R7 scheme). Offsets stashed
//      as half2 (18KB/CTA, preserves L1D for gathers). Compressed corner
//      indices + pair-packed bilinear FFMA2. launch_bounds(128,3).

#define Hn  160
#define Wn  160
#define CIN 32
#define COUT 32
#define HWs (Hn * Wn)
#define NPIX (8 * HWs)

#define WDCN_T_ELEMS (9 * 32 * 32)   // [k][c][o]         = 9216
#define WOFF_T_ELEMS (9 * 32 * 20)   // [k][c][oc pad 20] = 5760

__constant__ float c_wdcn[WDCN_T_ELEMS];   // 36 KB
__constant__ float c_woff[WOFF_T_ELEMS];   // 22.5 KB
__device__ float g_stage[WDCN_T_ELEMS + WOFF_T_ELEMS];

typedef unsigned long long u64;

__device__ __forceinline__ u64 pack2(float a, float b) {
    u64 r; asm("mov.b64 %0, {%1, %2};" : "=l"(r) : "f"(a), "f"(b)); return r;
}
__device__ __forceinline__ void unpack2(u64 v, float& a, float& b) {
    asm("mov.b64 {%0, %1}, %2;" : "=f"(a), "=f"(b) : "l"(v));
}
__device__ __forceinline__ void ffma2(u64& d, u64 a, u64 b) {
    asm("fma.rn.f32x2 %0, %1, %2, %0;" : "+l"(d) : "l"(a), "l"(b));
}

__global__ void prep_kernel(const float* __restrict__ w_off,
                            const float* __restrict__ w_dcn)
{
    const int i = blockIdx.x * 256 + threadIdx.x;
    if (i < WDCN_T_ELEMS) {   // [k][c][o]
        int k = i >> 10;
        int r = i & 1023;
        int c = r >> 5;
        int o = r & 31;
        g_stage[i] = w_dcn[o * 288 + c * 9 + k];
    }
    if (i < WOFF_T_ELEMS) {   // [k][c][oc pad 20]
        int k = i / 640;
        int r = i - k * 640;
        int c = r / 20;
        int oc = r - c * 20;
        g_stage[WDCN_T_ELEMS + i] = (oc < 18) ? w_off[oc * 288 + c * 9 + k] : 0.0f;
    }
}

__global__ __launch_bounds__(128, 3)
void dcn_fused_kernel(const float* __restrict__ x,
                      const float* __restrict__ b_off,
                      float* __restrict__ out)
{
    __shared__ unsigned int stash[4][128][9];   // half2(dy,dx), 18432 B

    const int tid = threadIdx.x;
    const int P0 = blockIdx.x * 512;           // 512 consecutive pixels/CTA
    const int b  = P0 / HWs;                   // 25600 % 512 == 0: no straddle
    const int hwBase = P0 - b * HWs;
    const float* xb = x + (size_t)b * CIN * HWs;

    int hw[4], hh[4], wwp[4];
#pragma unroll
    for (int p = 0; p < 4; p++) {
        hw[p]  = hwBase + tid + 128 * p;
        hh[p]  = hw[p] / Wn;
        wwp[p] = hw[p] - hh[p] * Wn;
    }

    // ================= Stage 1: offset conv (4 px) =================
    {
        u64 o2[4][9];
#pragma unroll
        for (int t = 0; t < 9; t++) {
            u64 bv = pack2(__ldg(&b_off[2 * t]), __ldg(&b_off[2 * t + 1]));
#pragma unroll
            for (int p = 0; p < 4; p++) o2[p][t] = bv;
        }

#pragma unroll
        for (int k = 0; k < 9; k++) {
            const int ky = k / 3, kx = k - 3 * (k / 3);
            int idx[4]; bool v[4];
#pragma unroll
            for (int p = 0; p < 4; p++) {
                int yy = hh[p] - 1 + ky;
                int xx = wwp[p] - 1 + kx;
                v[p] = (yy >= 0) && (yy < Hn) && (xx >= 0) && (xx < Wn);
                idx[p] = min(max(yy, 0), Hn - 1) * Wn + min(max(xx, 0), Wn - 1);
            }
#pragma unroll 4
            for (int c = 0; c < CIN; c++) {
                const float* xc = xb + c * HWs;
                u64 s[4];
#pragma unroll
                for (int p = 0; p < 4; p++) {
                    float xv = v[p] ? __ldg(xc + idx[p]) : 0.0f;
                    s[p] = pack2(xv, xv);
                }
                const ulonglong2* wc = (const ulonglong2*)(c_woff + k * 640 + c * 20);
#pragma unroll
                for (int j = 0; j < 4; j++) {
                    ulonglong2 q = wc[j];
#pragma unroll
                    for (int p = 0; p < 4; p++) {
                        ffma2(o2[p][2 * j],     s[p], q.x);
                        ffma2(o2[p][2 * j + 1], s[p], q.y);
                    }
                }
                ulonglong2 q4 = wc[4];
#pragma unroll
                for (int p = 0; p < 4; p++) ffma2(o2[p][8], s[p], q4.x);
            }
        }

#pragma unroll
        for (int p = 0; p < 4; p++)
#pragma unroll
            for (int t = 0; t < 9; t++) {
                float dy, dx; unpack2(o2[p][t], dy, dx);
                __half2 hv = __floats2half2_rn(dy, dx);
                stash[p][tid][t] = *(unsigned int*)&hv;
            }
    }

    // ================= Stage 2: deformable conv (4 px) =================
    u64 acc[4][16];
#pragma unroll
    for (int p = 0; p < 4; p++)
#pragma unroll
        for (int m = 0; m < 16; m++) acc[p][m] = 0ULL;

#pragma unroll
    for (int k = 0; k < 9; k++) {
        const int ky = k / 3, kx = k - 3 * (k / 3);

        float w00[4], w01[4], w10[4], w11[4];
        int i00[4], dxd[4], dyd[4];
#pragma unroll
        for (int p = 0; p < 4; p++) {
            unsigned int hb = stash[p][tid][k];
            __half2 hv = *(__half2*)&hb;
            float2 d = __half22float2(hv);
            const float py = (float)(hh[p] - 1 + ky) + d.x;
            const float px = (float)(wwp[p] - 1 + kx) + d.y;
            const float y0f = floorf(py), x0f = floorf(px);
            const float wy1 = py - y0f, wx1 = px - x0f;
            const float wy0 = 1.0f - wy1, wx0 = 1.0f - wx1;
            const float y1f = y0f + 1.0f, x1f = x0f + 1.0f;
            const bool vy0 = (y0f >= 0.0f) && (y0f <= (float)(Hn - 1));
            const bool vy1 = (y1f >= 0.0f) && (y1f <= (float)(Hn - 1));
            const bool vx0 = (x0f >= 0.0f) && (x0f <= (float)(Wn - 1));
            const bool vx1 = (x1f >= 0.0f) && (x1f <= (float)(Wn - 1));
            w00[p] = (vy0 && vx0) ? wy0 * wx0 : 0.0f;
            w01[p] = (vy0 && vx1) ? wy0 * wx1 : 0.0f;
            w10[p] = (vy1 && vx0) ? wy1 * wx0 : 0.0f;
            w11[p] = (vy1 && vx1) ? wy1 * wx1 : 0.0f;
            const int iy0 = min(max((int)y0f, 0), Hn - 1);
            const int iy1 = min(max((int)y1f, 0), Hn - 1);
            const int ix0 = min(max((int)x0f, 0), Wn - 1);
            const int ix1 = min(max((int)x1f, 0), Wn - 1);
            i00[p] = iy0 * Wn + ix0;
            dxd[p] = ix1 - ix0;
            dyd[p] = (iy1 - iy0) * Wn;
        }
        const u64 PW00 = pack2(w00[0], w00[1]), PW01 = pack2(w01[0], w01[1]);
        const u64 PW10 = pack2(w10[0], w10[1]), PW11 = pack2(w11[0], w11[1]);
        const u64 QW00 = pack2(w00[2], w00[3]), QW01 = pack2(w01[2], w01[3]);
        const u64 QW10 = pack2(w10[2], w10[3]), QW11 = pack2(w11[2], w11[3]);

#pragma unroll 4
        for (int c = 0; c < CIN; c++) {
            const float* xc = xb + c * HWs;
            float g00[4], g01[4], g10[4], g11[4];
#pragma unroll
            for (int p = 0; p < 4; p++) {
                const float* gp = xc + i00[p];
                g00[p] = __ldg(gp);
                g01[p] = __ldg(gp + dxd[p]);
                g10[p] = __ldg(gp + dyd[p]);
                g11[p] = __ldg(gp + dyd[p] + dxd[p]);
            }
            u64 v01 = 0ULL, v23 = 0ULL;
            ffma2(v01, PW00, pack2(g00[0], g00[1]));
            ffma2(v01, PW01, pack2(g01[0], g01[1]));
            ffma2(v01, PW10, pack2(g10[0], g10[1]));
            ffma2(v01, PW11, pack2(g11[0], g11[1]));
            ffma2(v23, QW00, pack2(g00[2], g00[3]));
            ffma2(v23, QW01, pack2(g01[2], g01[3]));
            ffma2(v23, QW10, pack2(g10[2], g10[3]));
            ffma2(v23, QW11, pack2(g11[2], g11[3]));
            float v0, v1, v2, v3;
            unpack2(v01, v0, v1);
            unpack2(v23, v2, v3);
            u64 sv[4];
            sv[0] = pack2(v0, v0); sv[1] = pack2(v1, v1);
            sv[2] = pack2(v2, v2); sv[3] = pack2(v3, v3);

            const ulonglong2* wc = (const ulonglong2*)(c_wdcn + k * 1024 + c * 32);
#pragma unroll
            for (int j = 0; j < 8; j++) {
                ulonglong2 q = wc[j];
#pragma unroll
                for (int p = 0; p < 4; p++) {
                    ffma2(acc[p][2 * j],     sv[p], q.x);
                    ffma2(acc[p][2 * j + 1], sv[p], q.y);
                }
            }
        }
    }

    // ================= Epilogue: ReLU + coalesced stores =================
    float* ob = out + (size_t)b * COUT * HWs;
#pragma unroll
    for (int p = 0; p < 4; p++) {
#pragma unroll
        for (int m = 0; m < 16; m++) {
            float a0, a1;
            unpack2(acc[p][m], a0, a1);
            ob[(2 * m)     * HWs + hw[p]] = fmaxf(a0, 0.0f);
            ob[(2 * m + 1) * HWs + hw[p]] = fmaxf(a1, 0.0f);
        }
    }
}

extern "C" void kernel_launch(void* const* d_in, const int* in_sizes, int n_in,
                              void* d_out, int out_size)
{
    const float* x     = (const float*)d_in[0];
    const float* w_off = (const float*)d_in[1];
    const float* b_off = (const float*)d_in[2];
    const float* w_dcn = (const float*)d_in[3];
    float* out = (float*)d_out;

    void* stage_dev = nullptr;
    cudaGetSymbolAddress(&stage_dev, g_stage);

    prep_kernel<<<(WDCN_T_ELEMS + 255) / 256, 256>>>(w_off, w_dcn);
    cudaMemcpyToSymbolAsync(c_wdcn, stage_dev,
                            WDCN_T_ELEMS * sizeof(float), 0,
                            cudaMemcpyDeviceToDevice, 0);
    cudaMemcpyToSymbolAsync(c_woff, (const char*)stage_dev + WDCN_T_ELEMS * sizeof(float),
                            WOFF_T_ELEMS * sizeof(float), 0,
                            cudaMemcpyDeviceToDevice, 0);

    const int blocks = NPIX / 512;    // 400
    dcn_fused_kernel<<<blocks, 128>>>(x, b_off, out);
}

// round 13
// speedup vs baseline: 1.8059x; 1.8059x over previous
#include <cuda_runtime.h>
#include <cuda_fp16.h>

// Deform_Conv_V1: fused offset-conv + deformable conv + ReLU.
// B=8, Cin=32, H=W=160, Cout=32, K=3, PAD=1.
// Inputs: x (8,32,160,160), w_off (18,32,3,3), b_off (18,), w_dcn (32,32,3,3)
// Output: (8,32,160,160) fp32.
//
// R13: R7 structure (2 px/thread, all weights in __constant__, FFMA2) with:
//      - pixel pairing (base+tid, base+128+tid): warp gather footprint per
//        corner LDG = 32 consecutive pixels (1-2 lines) vs 64 (2-3 lines)
//      - offset stash as half2 (9KB/CTA; R12 validated rel_err ~8e-5)
//      - compressed corner indices (i00 + dxd + dyd)

#define Hn  160
#define Wn  160
#define CIN 32
#define COUT 32
#define HWs (Hn * Wn)
#define NPIX (8 * HWs)

#define WDCN_T_ELEMS (9 * 32 * 32)   // [k][c][o]         = 9216
#define WOFF_T_ELEMS (9 * 32 * 20)   // [k][c][oc pad 20] = 5760

__constant__ float c_wdcn[WDCN_T_ELEMS];   // 36 KB
__constant__ float c_woff[WOFF_T_ELEMS];   // 22.5 KB
__device__ float g_stage[WDCN_T_ELEMS + WOFF_T_ELEMS];

typedef unsigned long long u64;

__device__ __forceinline__ u64 pack2(float a, float b) {
    u64 r; asm("mov.b64 %0, {%1, %2};" : "=l"(r) : "f"(a), "f"(b)); return r;
}
__device__ __forceinline__ void unpack2(u64 v, float& a, float& b) {
    asm("mov.b64 {%0, %1}, %2;" : "=f"(a), "=f"(b) : "l"(v));
}
__device__ __forceinline__ void ffma2(u64& d, u64 a, u64 b) {
    asm("fma.rn.f32x2 %0, %1, %2, %0;" : "+l"(d) : "l"(a), "l"(b));
}

__global__ void prep_kernel(const float* __restrict__ w_off,
                            const float* __restrict__ w_dcn)
{
    const int i = blockIdx.x * 256 + threadIdx.x;
    if (i < WDCN_T_ELEMS) {   // [k][c][o]
        int k = i >> 10;
        int r = i & 1023;
        int c = r >> 5;
        int o = r & 31;
        g_stage[i] = w_dcn[o * 288 + c * 9 + k];
    }
    if (i < WOFF_T_ELEMS) {   // [k][c][oc pad 20]
        int k = i / 640;
        int r = i - k * 640;
        int c = r / 20;
        int oc = r - c * 20;
        g_stage[WDCN_T_ELEMS + i] = (oc < 18) ? w_off[oc * 288 + c * 9 + k] : 0.0f;
    }
}

__global__ __launch_bounds__(128, 4)
void dcn_fused_kernel(const float* __restrict__ x,
                      const float* __restrict__ b_off,
                      float* __restrict__ out)
{
    __shared__ unsigned int stash[2][128][9];   // half2(dy,dx), 9216 B

    const int tid = threadIdx.x;
    const int P0 = blockIdx.x * 256;            // 256 consecutive pixels/CTA
    const int b  = P0 / HWs;                    // 25600 % 256 == 0: no straddle
    const int hw0 = P0 - b * HWs;
    const int hwA = hw0 + tid;
    const int hwB = hwA + 128;
    const int hA = hwA / Wn, wA = hwA - hA * Wn;
    const int hB = hwB / Wn, wB = hwB - hB * Wn;
    const float* xb = x + (size_t)b * CIN * HWs;

    // ================= Stage 1: offset conv (fp32 exact) =================
    {
        u64 oA[9], oB[9];
#pragma unroll
        for (int p = 0; p < 9; p++) {
            u64 bv = pack2(__ldg(&b_off[2 * p]), __ldg(&b_off[2 * p + 1]));
            oA[p] = bv; oB[p] = bv;
        }
#pragma unroll
        for (int k = 0; k < 9; k++) {
            const int ky = k / 3, kx = k - 3 * (k / 3);
            const int yA = hA - 1 + ky, xAc = wA - 1 + kx;
            const int yB = hB - 1 + ky, xBc = wB - 1 + kx;
            const bool vA = (yA >= 0) && (yA < Hn) && (xAc >= 0) && (xAc < Wn);
            const bool vB = (yB >= 0) && (yB < Hn) && (xBc >= 0) && (xBc < Wn);
            const int iA = min(max(yA, 0), Hn - 1) * Wn + min(max(xAc, 0), Wn - 1);
            const int iB = min(max(yB, 0), Hn - 1) * Wn + min(max(xBc, 0), Wn - 1);
#pragma unroll 4
            for (int c = 0; c < CIN; c++) {
                const float* xc = xb + c * HWs;
                const float fA = vA ? __ldg(xc + iA) : 0.0f;
                const float fB = vB ? __ldg(xc + iB) : 0.0f;
                const u64 xa = pack2(fA, fA), xbv = pack2(fB, fB);
                const ulonglong2* wc = (const ulonglong2*)(c_woff + k * 640 + c * 20);
#pragma unroll
                for (int j = 0; j < 4; j++) {
                    ulonglong2 q = wc[j];
                    ffma2(oA[2 * j],     xa,  q.x);
                    ffma2(oA[2 * j + 1], xa,  q.y);
                    ffma2(oB[2 * j],     xbv, q.x);
                    ffma2(oB[2 * j + 1], xbv, q.y);
                }
                ulonglong2 q4 = wc[4];
                ffma2(oA[8], xa,  q4.x);
                ffma2(oB[8], xbv, q4.x);
            }
        }
#pragma unroll
        for (int p = 0; p < 9; p++) {
            float dy, dx;
            unpack2(oA[p], dy, dx);
            __half2 h2 = __floats2half2_rn(dy, dx);
            stash[0][tid][p] = *(unsigned int*)&h2;
            unpack2(oB[p], dy, dx);
            h2 = __floats2half2_rn(dy, dx);
            stash[1][tid][p] = *(unsigned int*)&h2;
        }
    }

    // ================= Stage 2: deformable conv =================
    u64 acca[16], accb[16];
#pragma unroll
    for (int m = 0; m < 16; m++) { acca[m] = 0ULL; accb[m] = 0ULL; }

#pragma unroll
    for (int k = 0; k < 9; k++) {
        const int ky = k / 3, kx = k - 3 * (k / 3);

        float aw00, aw01, aw10, aw11; int aI, aDx, aDy;
        {
            unsigned int hb = stash[0][tid][k];
            float2 d = __half22float2(*(__half2*)&hb);
            const float py = (float)(hA - 1 + ky) + d.x;
            const float px = (float)(wA - 1 + kx) + d.y;
            const float y0f = floorf(py), x0f = floorf(px);
            const float wy1 = py - y0f, wx1 = px - x0f;
            const float wy0 = 1.0f - wy1, wx0 = 1.0f - wx1;
            const float y1f = y0f + 1.0f, x1f = x0f + 1.0f;
            const bool vy0 = (y0f >= 0.0f) && (y0f <= (float)(Hn - 1));
            const bool vy1 = (y1f >= 0.0f) && (y1f <= (float)(Hn - 1));
            const bool vx0 = (x0f >= 0.0f) && (x0f <= (float)(Wn - 1));
            const bool vx1 = (x1f >= 0.0f) && (x1f <= (float)(Wn - 1));
            aw00 = (vy0 && vx0) ? wy0 * wx0 : 0.0f;
            aw01 = (vy0 && vx1) ? wy0 * wx1 : 0.0f;
            aw10 = (vy1 && vx0) ? wy1 * wx0 : 0.0f;
            aw11 = (vy1 && vx1) ? wy1 * wx1 : 0.0f;
            const int iy0 = min(max((int)y0f, 0), Hn - 1);
            const int iy1 = min(max((int)y1f, 0), Hn - 1);
            const int ix0 = min(max((int)x0f, 0), Wn - 1);
            const int ix1 = min(max((int)x1f, 0), Wn - 1);
            aI  = iy0 * Wn + ix0;
            aDx = ix1 - ix0;
            aDy = (iy1 - iy0) * Wn;
        }
        float bw00, bw01, bw10, bw11; int bI, bDx, bDy;
        {
            unsigned int hb = stash[1][tid][k];
            float2 d = __half22float2(*(__half2*)&hb);
            const float py = (float)(hB - 1 + ky) + d.x;
            const float px = (float)(wB - 1 + kx) + d.y;
            const float y0f = floorf(py), x0f = floorf(px);
            const float wy1 = py - y0f, wx1 = px - x0f;
            const float wy0 = 1.0f - wy1, wx0 = 1.0f - wx1;
            const float y1f = y0f + 1.0f, x1f = x0f + 1.0f;
            const bool vy0 = (y0f >= 0.0f) && (y0f <= (float)(Hn - 1));
            const bool vy1 = (y1f >= 0.0f) && (y1f <= (float)(Hn - 1));
            const bool vx0 = (x0f >= 0.0f) && (x0f <= (float)(Wn - 1));
            const bool vx1 = (x1f >= 0.0f) && (x1f <= (float)(Wn - 1));
            bw00 = (vy0 && vx0) ? wy0 * wx0 : 0.0f;
            bw01 = (vy0 && vx1) ? wy0 * wx1 : 0.0f;
            bw10 = (vy1 && vx0) ? wy1 * wx0 : 0.0f;
            bw11 = (vy1 && vx1) ? wy1 * wx1 : 0.0f;
            const int iy0 = min(max((int)y0f, 0), Hn - 1);
            const int iy1 = min(max((int)y1f, 0), Hn - 1);
            const int ix0 = min(max((int)x0f, 0), Wn - 1);
            const int ix1 = min(max((int)x1f, 0), Wn - 1);
            bI  = iy0 * Wn + ix0;
            bDx = ix1 - ix0;
            bDy = (iy1 - iy0) * Wn;
        }

        const u64 W00 = pack2(aw00, bw00);
        const u64 W01 = pack2(aw01, bw01);
        const u64 W10 = pack2(aw10, bw10);
        const u64 W11 = pack2(aw11, bw11);

#pragma unroll 4
        for (int c = 0; c < CIN; c++) {
            const float* xc = xb + c * HWs;
            const float* ga = xc + aI;
            const float* gb = xc + bI;
            const u64 P00 = pack2(__ldg(ga),             __ldg(gb));
            const u64 P01 = pack2(__ldg(ga + aDx),       __ldg(gb + bDx));
            const u64 P10 = pack2(__ldg(ga + aDy),       __ldg(gb + bDy));
            const u64 P11 = pack2(__ldg(ga + aDy + aDx), __ldg(gb + bDy + bDx));
            u64 vab = 0ULL;
            ffma2(vab, W00, P00);
            ffma2(vab, W01, P01);
            ffma2(vab, W10, P10);
            ffma2(vab, W11, P11);
            float va, vb; unpack2(vab, va, vb);
            const u64 va2 = pack2(va, va);
            const u64 vb2 = pack2(vb, vb);
            const ulonglong2* wc = (const ulonglong2*)(c_wdcn + k * 1024 + c * 32);
#pragma unroll
            for (int j = 0; j < 8; j++) {
                ulonglong2 q = wc[j];
                ffma2(acca[2 * j],     va2, q.x);
                ffma2(acca[2 * j + 1], va2, q.y);
                ffma2(accb[2 * j],     vb2, q.x);
                ffma2(accb[2 * j + 1], vb2, q.y);
            }
        }
    }

    // ================= Epilogue: ReLU + coalesced STG.32 =================
    float* ob = out + (size_t)b * COUT * HWs;
#pragma unroll
    for (int m = 0; m < 16; m++) {
        float a0, a1, c0, c1;
        unpack2(acca[m], a0, a1);
        unpack2(accb[m], c0, c1);
        ob[(2 * m)     * HWs + hwA] = fmaxf(a0, 0.0f);
        ob[(2 * m + 1) * HWs + hwA] = fmaxf(a1, 0.0f);
        ob[(2 * m)     * HWs + hwB] = fmaxf(c0, 0.0f);
        ob[(2 * m + 1) * HWs + hwB] = fmaxf(c1, 0.0f);
    }
}

extern "C" void kernel_launch(void* const* d_in, const int* in_sizes, int n_in,
                              void* d_out, int out_size)
{
    const float* x     = (const float*)d_in[0];
    const float* w_off = (const float*)d_in[1];
    const float* b_off = (const float*)d_in[2];
    const float* w_dcn = (const float*)d_in[3];
    float* out = (float*)d_out;

    void* stage_dev = nullptr;
    cudaGetSymbolAddress(&stage_dev, g_stage);

    prep_kernel<<<(WDCN_T_ELEMS + 255) / 256, 256>>>(w_off, w_dcn);
    cudaMemcpyToSymbolAsync(c_wdcn, stage_dev,
                            WDCN_T_ELEMS * sizeof(float), 0,
                            cudaMemcpyDeviceToDevice, 0);
    cudaMemcpyToSymbolAsync(c_woff, (const char*)stage_dev + WDCN_T_ELEMS * sizeof(float),
                            WOFF_T_ELEMS * sizeof(float), 0,
                            cudaMemcpyDeviceToDevice, 0);

    const int blocks = NPIX / 256;    // 800
    dcn_fused_kernel<<<blocks, 128>>>(x, b_off, out);
}